// round 16
// baseline (speedup 1.0000x reference)
#include <cuda_runtime.h>
#include <cuda_fp16.h>
#include <math.h>
#include <stdint.h>

// Problem constants (fixed shapes)
#define Nn    20000
#define Ee    640000
#define ETOT  (Ee + Nn)
#define Gg    64
#define DIN   256
#define Hh    4
#define Cc    64
#define HC    256
#define DOUT  32

// ---------------- scratch (device globals; no allocation) ----------------
__device__ __align__(16) __half g_hh[Nn * HC];   // h fp16 (gather source)
__device__ __align__(16) float  g_x[Nn * HC];    // layer-1 output fp32 (GEMM-2 A)
__device__ __align__(16) float  g_es[Nn * Hh];
__device__ __align__(16) float  g_ed[Nn * Hh];
__device__ int   g_deg[Nn];
__device__ int   g_off[Nn + 1];
__device__ int   g_cur[Nn];
__device__ int   g_csr[ETOT];
__device__ float g_sums[Gg * DOUT];
__device__ int   g_cnt[Gg];

// ---------------- helpers ----------------
__device__ __forceinline__ float lrelu(float x) { return x > 0.0f ? x : 0.2f * x; }

__device__ __forceinline__ unsigned long long dupr(float v) {
    unsigned long long d;
    asm("mov.b64 %0, {%1, %1};" : "=l"(d) : "f"(v));
    return d;
}

#define FMA2(d, a, b) asm("fma.rn.f32x2 %0, %1, %2, %0;" : "+l"(d) : "l"(a), "l"(b))

__device__ __forceinline__ void cpasync16(uint32_t dst, const void* src) {
    asm volatile("cp.async.ca.shared.global [%0], [%1], 16;" :: "r"(dst), "l"(src));
}
#define CP_COMMIT() asm volatile("cp.async.commit_group;" ::: "memory")
#define CP_WAIT0()  asm volatile("cp.async.wait_group 0;" ::: "memory")

// ---------------- zero scratch (deg=1 accounts for self-loop) ----------------
__global__ void k_zero() {
    int i = blockIdx.x * blockDim.x + threadIdx.x;
    if (i < Nn) g_deg[i] = 1;
    if (i < Gg * DOUT) g_sums[i] = 0.0f;
    if (i < Gg) g_cnt[i] = 0;
}

// ---------------- CSR build (8 edges per thread) ----------------
__global__ void k_count(const int* __restrict__ ei) {
    int t = blockIdx.x * blockDim.x + threadIdx.x;
    if (t >= Ee / 8) return;
    int4 a = *(const int4*)(ei + Ee + t * 8);
    int4 b = *(const int4*)(ei + Ee + t * 8 + 4);
    atomicAdd(&g_deg[a.x], 1);
    atomicAdd(&g_deg[a.y], 1);
    atomicAdd(&g_deg[a.z], 1);
    atomicAdd(&g_deg[a.w], 1);
    atomicAdd(&g_deg[b.x], 1);
    atomicAdd(&g_deg[b.y], 1);
    atomicAdd(&g_deg[b.z], 1);
    atomicAdd(&g_deg[b.w], 1);
}

__global__ void k_scan() {
    __shared__ int sh[1024];
    const int CH = (Nn + 1023) / 1024;  // 20
    int t = threadIdx.x;
    int base = t * CH;
    int s = 0;
#pragma unroll
    for (int i = 0; i < CH; i++) {
        int idx = base + i;
        if (idx < Nn) s += g_deg[idx];
    }
    sh[t] = s;
    __syncthreads();
    for (int off = 1; off < 1024; off <<= 1) {
        int v = 0;
        if (t >= off) v = sh[t - off];
        __syncthreads();
        sh[t] += v;
        __syncthreads();
    }
    int run = sh[t] - s;
#pragma unroll
    for (int i = 0; i < CH; i++) {
        int idx = base + i;
        if (idx < Nn) {
            g_off[idx] = run;
            g_cur[idx] = run;
            run += g_deg[idx];
        }
    }
    if (t == 1023) g_off[Nn] = sh[1023];
}

__global__ void k_scatter(const int* __restrict__ ei) {
    int t = blockIdx.x * blockDim.x + threadIdx.x;
    if (t < Ee / 8) {
        int4 sa = *(const int4*)(ei + t * 8);
        int4 sb = *(const int4*)(ei + t * 8 + 4);
        int4 da = *(const int4*)(ei + Ee + t * 8);
        int4 db = *(const int4*)(ei + Ee + t * 8 + 4);
        int p0 = atomicAdd(&g_cur[da.x], 1);
        int p1 = atomicAdd(&g_cur[da.y], 1);
        int p2 = atomicAdd(&g_cur[da.z], 1);
        int p3 = atomicAdd(&g_cur[da.w], 1);
        int p4 = atomicAdd(&g_cur[db.x], 1);
        int p5 = atomicAdd(&g_cur[db.y], 1);
        int p6 = atomicAdd(&g_cur[db.z], 1);
        int p7 = atomicAdd(&g_cur[db.w], 1);
        g_csr[p0] = sa.x; g_csr[p1] = sa.y; g_csr[p2] = sa.z; g_csr[p3] = sa.w;
        g_csr[p4] = sb.x; g_csr[p5] = sb.y; g_csr[p6] = sb.z; g_csr[p7] = sb.w;
    } else {
        int n = t - Ee / 8;
        if (n < Nn) g_csr[atomicAdd(&g_cur[n], 1)] = n;
    }
}

// ---------------- GEMM + fused attention scores ----------------
// 128x128 tile, 8x8 per thread (LDS-balanced), cp.async double-buffered loads.
// A stored row-major [m][k] with stride 20 (pad): conflict-free scalar reads.
#define BM 128
#define BN 128
#define BK 16
#define ASTRIDE 20

__global__ void __launch_bounds__(256, 2) k_gemm(const float* __restrict__ A_ext,
                                                 const float* __restrict__ B,
                                                 const float* __restrict__ asrc,
                                                 const float* __restrict__ adst,
                                                 int useExt) {
    const float* __restrict__ A = useExt ? A_ext : g_x;

    __shared__ __align__(16) float As[2][BM][ASTRIDE];  // row-major A, padded
    __shared__ __align__(16) float Bs[2][BK][BN];       // natural B

    int tid = threadIdx.x;
    int bm = blockIdx.x * BM;
    int bn = blockIdx.y * BN;
    int ty = tid >> 4;
    int tx = tid & 15;

    unsigned long long acc[8][4];
#pragma unroll
    for (int i = 0; i < 8; i++)
#pragma unroll
        for (int j = 0; j < 4; j++) acc[i][j] = 0ULL;

    // A loader: thread -> (row = tid>>1, kseg = (tid&1)*8); OOB rows clamped
    // (their results are discarded by the guarded epilogue).
    int la_row = tid >> 1;
    int la_ks  = (tid & 1) * 8;
    int arow = bm + la_row;
    if (arow >= Nn) arow = Nn - 1;
    const float* gA = A + (size_t)arow * HC + la_ks;
    // B loader: thread -> (k = tid>>4, n0 = (tid&15)*8)
    int lb_k  = tid >> 4;
    int lb_n0 = (tid & 15) * 8;
    const float* gB = B + (size_t)lb_k * HC + bn + lb_n0;

    uint32_t sA[2], sB[2];
    sA[0] = (uint32_t)__cvta_generic_to_shared(&As[0][la_row][la_ks]);
    sA[1] = (uint32_t)__cvta_generic_to_shared(&As[1][la_row][la_ks]);
    sB[0] = (uint32_t)__cvta_generic_to_shared(&Bs[0][lb_k][lb_n0]);
    sB[1] = (uint32_t)__cvta_generic_to_shared(&Bs[1][lb_k][lb_n0]);

    // prologue: tile 0 via cp.async
    cpasync16(sA[0], gA);
    cpasync16(sA[0] + 16, gA + 4);
    cpasync16(sB[0], gB);
    cpasync16(sB[0] + 16, gB + 4);
    CP_COMMIT();
    CP_WAIT0();
    __syncthreads();

    int buf = 0;
    for (int k0 = 0; k0 < 256; k0 += BK) {
        bool more = (k0 + BK) < 256;
        if (more) {
            int nb = buf ^ 1;
            const float* gAn = gA + k0 + BK;
            const float* gBn = gB + (size_t)(k0 + BK) * HC;
            cpasync16(sA[nb], gAn);
            cpasync16(sA[nb] + 16, gAn + 4);
            cpasync16(sB[nb], gBn);
            cpasync16(sB[nb] + 16, gBn + 4);
            CP_COMMIT();
        }

#pragma unroll
        for (int kk = 0; kk < BK; kk++) {
            unsigned long long ad[8];
#pragma unroll
            for (int m = 0; m < 8; m++)
                ad[m] = dupr(As[buf][ty * 8 + m][kk]);
            ulonglong2 b01 = *(const ulonglong2*)&Bs[buf][kk][tx * 8];
            ulonglong2 b23 = *(const ulonglong2*)&Bs[buf][kk][tx * 8 + 4];
            unsigned long long bp[4] = {b01.x, b01.y, b23.x, b23.y};
#pragma unroll
            for (int m = 0; m < 8; m++) {
                FMA2(acc[m][0], ad[m], bp[0]);
                FMA2(acc[m][1], ad[m], bp[1]);
                FMA2(acc[m][2], ad[m], bp[2]);
                FMA2(acc[m][3], ad[m], bp[3]);
            }
        }

        if (more) {
            CP_WAIT0();
            __syncthreads();
            buf ^= 1;
        }
    }

    float asr[8], adr[8];
#pragma unroll
    for (int j = 0; j < 8; j++) {
        asr[j] = __ldg(&asrc[bn + tx * 8 + j]);
        adr[j] = __ldg(&adst[bn + tx * 8 + j]);
    }
    int head = (bn >> 6) + (tx >> 3);   // 2 heads per BN=128

#pragma unroll
    for (int m = 0; m < 8; m++) {
        int row = bm + ty * 8 + m;
        float f[8];
        f[0] = __uint_as_float((unsigned)acc[m][0]);
        f[1] = __uint_as_float((unsigned)(acc[m][0] >> 32));
        f[2] = __uint_as_float((unsigned)acc[m][1]);
        f[3] = __uint_as_float((unsigned)(acc[m][1] >> 32));
        f[4] = __uint_as_float((unsigned)acc[m][2]);
        f[5] = __uint_as_float((unsigned)(acc[m][2] >> 32));
        f[6] = __uint_as_float((unsigned)acc[m][3]);
        f[7] = __uint_as_float((unsigned)(acc[m][3] >> 32));

        float ps = 0.f, pd = 0.f;
#pragma unroll
        for (int j = 0; j < 8; j++) {
            ps = fmaf(f[j], asr[j], ps);
            pd = fmaf(f[j], adr[j], pd);
        }
#pragma unroll
        for (int o = 1; o < 8; o <<= 1) {
            ps += __shfl_xor_sync(0xFFFFFFFFu, ps, o);
            pd += __shfl_xor_sync(0xFFFFFFFFu, pd, o);
        }

        if (row < Nn) {
            __half2 ph[4];
            ph[0] = __floats2half2_rn(f[0], f[1]);
            ph[1] = __floats2half2_rn(f[2], f[3]);
            ph[2] = __floats2half2_rn(f[4], f[5]);
            ph[3] = __floats2half2_rn(f[6], f[7]);
            *(uint4*)&g_hh[(size_t)row * HC + bn + tx * 8] = *(uint4*)ph;
            if ((tx & 7) == 0) {
                g_es[row * Hh + head] = ps;
                g_ed[row * Hh + head] = pd;
            }
        }
    }
}

// ---------------- GAT aggregation: warp per dst node, SINGLE PASS ----------
// mode 0: write fp32 g_x; mode 1: fused projection + per-graph pooling.
__global__ void __launch_bounds__(256) k_agg(const float* __restrict__ bias,
                                             const float* __restrict__ Wp,
                                             const int* __restrict__ batch,
                                             int mode) {
    int w = (blockIdx.x * blockDim.x + threadIdx.x) >> 5;
    if (w >= Nn) return;
    int lane = threadIdx.x & 31;

    int r0 = g_off[w];
    int r1 = g_off[w + 1];
    float4 ed4 = *(const float4*)(g_ed + w * Hh);

    int hsel = lane >> 3;
    float edh = (hsel == 0) ? ed4.x : (hsel == 1) ? ed4.y : (hsel == 2) ? ed4.z : ed4.w;

    const float* es = (const float*)g_es;

    float a0 = 0.f, a1 = 0.f, a2 = 0.f, a3 = 0.f, a4 = 0.f, a5 = 0.f, a6 = 0.f, a7 = 0.f;
    float den = 0.f;
    int i = r0;
#define ACC_EDGE(qq, ww)                                            \
    {                                                               \
        float2 f0 = __half22float2(*(__half2*)&qq.x);               \
        float2 f1 = __half22float2(*(__half2*)&qq.y);               \
        float2 f2 = __half22float2(*(__half2*)&qq.z);               \
        float2 f3 = __half22float2(*(__half2*)&qq.w);               \
        a0 = fmaf(ww, f0.x, a0); a1 = fmaf(ww, f0.y, a1);           \
        a2 = fmaf(ww, f1.x, a2); a3 = fmaf(ww, f1.y, a3);           \
        a4 = fmaf(ww, f2.x, a4); a5 = fmaf(ww, f2.y, a5);           \
        a6 = fmaf(ww, f3.x, a6); a7 = fmaf(ww, f3.y, a7);           \
    }
    for (; i + 4 <= r1; i += 4) {
        int s0 = __ldg(&g_csr[i]);
        int s1 = __ldg(&g_csr[i + 1]);
        int s2 = __ldg(&g_csr[i + 2]);
        int s3 = __ldg(&g_csr[i + 3]);
        float e0 = __ldg(&es[s0 * 4 + hsel]);
        float e1 = __ldg(&es[s1 * 4 + hsel]);
        float e2 = __ldg(&es[s2 * 4 + hsel]);
        float e3 = __ldg(&es[s3 * 4 + hsel]);
        uint4 q0 = *(const uint4*)(g_hh + (size_t)s0 * HC + lane * 8);
        uint4 q1 = *(const uint4*)(g_hh + (size_t)s1 * HC + lane * 8);
        uint4 q2 = *(const uint4*)(g_hh + (size_t)s2 * HC + lane * 8);
        uint4 q3 = *(const uint4*)(g_hh + (size_t)s3 * HC + lane * 8);
        float w0 = __expf(lrelu(e0 + edh));
        float w1 = __expf(lrelu(e1 + edh));
        float w2 = __expf(lrelu(e2 + edh));
        float w3 = __expf(lrelu(e3 + edh));
        den += w0 + w1 + w2 + w3;
        ACC_EDGE(q0, w0);
        ACC_EDGE(q1, w1);
        ACC_EDGE(q2, w2);
        ACC_EDGE(q3, w3);
    }
    for (; i < r1; i++) {
        int s0 = __ldg(&g_csr[i]);
        float e0 = __ldg(&es[s0 * 4 + hsel]);
        uint4 q0 = *(const uint4*)(g_hh + (size_t)s0 * HC + lane * 8);
        float w0 = __expf(lrelu(e0 + edh));
        den += w0;
        ACC_EDGE(q0, w0);
    }
#undef ACC_EDGE

    float inv = 1.0f / fmaxf(den, 1e-16f);

    int b0 = lane * 8;
    const float4* bp4 = (const float4*)(bias + b0);
    float4 bb0 = bp4[0], bb1 = bp4[1];
    float v[8];
    v[0] = fmaxf(a0 * inv + bb0.x, 0.0f);
    v[1] = fmaxf(a1 * inv + bb0.y, 0.0f);
    v[2] = fmaxf(a2 * inv + bb0.z, 0.0f);
    v[3] = fmaxf(a3 * inv + bb0.w, 0.0f);
    v[4] = fmaxf(a4 * inv + bb1.x, 0.0f);
    v[5] = fmaxf(a5 * inv + bb1.y, 0.0f);
    v[6] = fmaxf(a6 * inv + bb1.z, 0.0f);
    v[7] = fmaxf(a7 * inv + bb1.w, 0.0f);

    if (mode == 0) {
        float* op = g_x + (size_t)w * HC + b0;
        *(float4*)op = make_float4(v[0], v[1], v[2], v[3]);
        *(float4*)(op + 4) = make_float4(v[4], v[5], v[6], v[7]);
    } else {
        float acc = 0.0f;
#pragma unroll 4
        for (int sl = 0; sl < 32; sl++) {
#pragma unroll
            for (int j = 0; j < 8; j++) {
                float xb = __shfl_sync(0xFFFFFFFFu, v[j], sl);
                acc = fmaf(xb, __ldg(&Wp[(size_t)(sl * 8 + j) * DOUT + lane]), acc);
            }
        }
        int g = __ldg(&batch[w]);
        atomicAdd(&g_sums[g * DOUT + lane], acc);
        if (lane == 0) atomicAdd(&g_cnt[g], 1);
    }
}

// ---------------- final mean + bias ----------------
__global__ void k_fin(float* __restrict__ out, const float* __restrict__ bp) {
    int i = blockIdx.x * blockDim.x + threadIdx.x;
    if (i >= Gg * DOUT) return;
    int g = i / DOUT, j = i % DOUT;
    out[i] = g_sums[i] / fmaxf((float)g_cnt[g], 1.0f) + bp[j];
}

// ---------------- launch ----------------
extern "C" void kernel_launch(void* const* d_in, const int* in_sizes, int n_in,
                              void* d_out, int out_size) {
    const float* x     = (const float*)d_in[0];
    const int*   ei    = (const int*)d_in[1];
    const int*   batch = (const int*)d_in[2];
    const float* W1    = (const float*)d_in[3];
    const float* as1   = (const float*)d_in[4];
    const float* ad1   = (const float*)d_in[5];
    const float* b1    = (const float*)d_in[6];
    const float* W2    = (const float*)d_in[7];
    const float* as2   = (const float*)d_in[8];
    const float* ad2   = (const float*)d_in[9];
    const float* b2    = (const float*)d_in[10];
    const float* Wp    = (const float*)d_in[11];
    const float* bp    = (const float*)d_in[12];
    float* out = (float*)d_out;

    (void)in_sizes; (void)n_in; (void)out_size;

    dim3 ggrid((Nn + BM - 1) / BM, HC / BN);  // (157, 2)
    int warp_blocks = (Nn * 32 + 255) / 256;  // 2500

    // Order keeps k_gemm as ncu's captured (4th) launch.
    k_zero<<<(Nn + 255) / 256, 256>>>();
    k_count<<<(Ee / 8 + 255) / 256, 256>>>(ei);
    k_scan<<<1, 1024>>>();
    k_gemm<<<ggrid, 256>>>(x, W1, as1, ad1, 1);          // layer-1 GEMM
    k_scatter<<<(Ee / 8 + Nn + 255) / 256, 256>>>(ei);
    k_agg<<<warp_blocks, 256>>>(b1, Wp, batch, 0);       // layer-1 agg -> g_x

    k_gemm<<<ggrid, 256>>>(nullptr, W2, as2, ad2, 0);    // layer-2 GEMM
    k_agg<<<warp_blocks, 256>>>(b2, Wp, batch, 1);       // layer-2 agg + proj + pool

    k_fin<<<(Gg * DOUT + 255) / 256, 256>>>(out, bp);
}

// round 17
// speedup vs baseline: 1.1035x; 1.1035x over previous
#include <cuda_runtime.h>
#include <cuda_fp16.h>
#include <math.h>
#include <stdint.h>

// Problem constants (fixed shapes)
#define Nn    20000
#define Ee    640000
#define ETOT  (Ee + Nn)
#define Gg    64
#define DIN   256
#define Hh    4
#define Cc    64
#define HC    256
#define DOUT  32

// ---------------- scratch (device globals; no allocation) ----------------
__device__ __align__(16) __half g_hh[Nn * HC];   // h fp16 (gather source)
__device__ __align__(16) float  g_x[Nn * HC];    // layer-1 output fp32 (GEMM-2 A)
__device__ __align__(16) float  g_es[Nn * Hh];
__device__ __align__(16) float  g_ed[Nn * Hh];
__device__ int   g_deg[Nn];
__device__ int   g_off[Nn + 1];
__device__ int   g_cur[Nn];
__device__ int   g_csr[ETOT];
__device__ float g_sums[Gg * DOUT];
__device__ int   g_cnt[Gg];

// ---------------- helpers ----------------
__device__ __forceinline__ float lrelu(float x) { return x > 0.0f ? x : 0.2f * x; }

__device__ __forceinline__ unsigned long long dupr(float v) {
    unsigned long long d;
    asm("mov.b64 %0, {%1, %1};" : "=l"(d) : "f"(v));
    return d;
}

#define FMA2(d, a, b) asm("fma.rn.f32x2 %0, %1, %2, %0;" : "+l"(d) : "l"(a), "l"(b))

// ---------------- zero scratch (deg=1 accounts for self-loop) ----------------
__global__ void k_zero() {
    int i = blockIdx.x * blockDim.x + threadIdx.x;
    if (i < Nn) g_deg[i] = 1;
    if (i < Gg * DOUT) g_sums[i] = 0.0f;
    if (i < Gg) g_cnt[i] = 0;
}

// ---------------- CSR build (8 edges per thread) ----------------
__global__ void k_count(const int* __restrict__ ei) {
    int t = blockIdx.x * blockDim.x + threadIdx.x;
    if (t >= Ee / 8) return;
    int4 a = *(const int4*)(ei + Ee + t * 8);
    int4 b = *(const int4*)(ei + Ee + t * 8 + 4);
    atomicAdd(&g_deg[a.x], 1);
    atomicAdd(&g_deg[a.y], 1);
    atomicAdd(&g_deg[a.z], 1);
    atomicAdd(&g_deg[a.w], 1);
    atomicAdd(&g_deg[b.x], 1);
    atomicAdd(&g_deg[b.y], 1);
    atomicAdd(&g_deg[b.z], 1);
    atomicAdd(&g_deg[b.w], 1);
}

__global__ void k_scan() {
    __shared__ int sh[1024];
    const int CH = (Nn + 1023) / 1024;  // 20
    int t = threadIdx.x;
    int base = t * CH;
    int s = 0;
#pragma unroll
    for (int i = 0; i < CH; i++) {
        int idx = base + i;
        if (idx < Nn) s += g_deg[idx];
    }
    sh[t] = s;
    __syncthreads();
    for (int off = 1; off < 1024; off <<= 1) {
        int v = 0;
        if (t >= off) v = sh[t - off];
        __syncthreads();
        sh[t] += v;
        __syncthreads();
    }
    int run = sh[t] - s;
#pragma unroll
    for (int i = 0; i < CH; i++) {
        int idx = base + i;
        if (idx < Nn) {
            g_off[idx] = run;
            g_cur[idx] = run;
            run += g_deg[idx];
        }
    }
    if (t == 1023) g_off[Nn] = sh[1023];
}

__global__ void k_scatter(const int* __restrict__ ei) {
    int t = blockIdx.x * blockDim.x + threadIdx.x;
    if (t < Ee / 8) {
        int4 sa = *(const int4*)(ei + t * 8);
        int4 sb = *(const int4*)(ei + t * 8 + 4);
        int4 da = *(const int4*)(ei + Ee + t * 8);
        int4 db = *(const int4*)(ei + Ee + t * 8 + 4);
        int p0 = atomicAdd(&g_cur[da.x], 1);
        int p1 = atomicAdd(&g_cur[da.y], 1);
        int p2 = atomicAdd(&g_cur[da.z], 1);
        int p3 = atomicAdd(&g_cur[da.w], 1);
        int p4 = atomicAdd(&g_cur[db.x], 1);
        int p5 = atomicAdd(&g_cur[db.y], 1);
        int p6 = atomicAdd(&g_cur[db.z], 1);
        int p7 = atomicAdd(&g_cur[db.w], 1);
        g_csr[p0] = sa.x; g_csr[p1] = sa.y; g_csr[p2] = sa.z; g_csr[p3] = sa.w;
        g_csr[p4] = sb.x; g_csr[p5] = sb.y; g_csr[p6] = sb.z; g_csr[p7] = sb.w;
    } else {
        int n = t - Ee / 8;
        if (n < Nn) g_csr[atomicAdd(&g_cur[n], 1)] = n;
    }
}

// ---------------- GEMM + fused attention scores (proven R12) ----------------
#define BM 128
#define BN 128
#define BK 16

__global__ void __launch_bounds__(256, 2) k_gemm(const float* __restrict__ A_ext,
                                                 const float* __restrict__ B,
                                                 const float* __restrict__ asrc,
                                                 const float* __restrict__ adst,
                                                 int useExt) {
    const float* __restrict__ A = useExt ? A_ext : g_x;

    __shared__ __align__(16) float As[2][BK][BM];
    __shared__ __align__(16) float Bs[2][BK][BN];

    int tid = threadIdx.x;
    int bm = blockIdx.x * BM;
    int bn = blockIdx.y * BN;
    int ty = tid >> 4;
    int tx = tid & 15;

    unsigned long long acc[8][4];
#pragma unroll
    for (int i = 0; i < 8; i++)
#pragma unroll
        for (int j = 0; j < 4; j++) acc[i][j] = 0ULL;

    int la_row = tid >> 1;
    int la_ks  = (tid & 1) * 8;
    bool arow_ok = (bm + la_row) < Nn;
    const float* Abase = A + (size_t)(bm + la_row) * HC + la_ks;
    int lb_k  = tid >> 4;
    int lb_n0 = (tid & 15) * 8;
    const float* Bbase = B + (size_t)lb_k * HC + bn + lb_n0;

    {
        float4 va0 = make_float4(0.f, 0.f, 0.f, 0.f), va1 = va0;
        if (arow_ok) { va0 = *(const float4*)Abase; va1 = *(const float4*)(Abase + 4); }
        As[0][la_ks + 0][la_row] = va0.x; As[0][la_ks + 1][la_row] = va0.y;
        As[0][la_ks + 2][la_row] = va0.z; As[0][la_ks + 3][la_row] = va0.w;
        As[0][la_ks + 4][la_row] = va1.x; As[0][la_ks + 5][la_row] = va1.y;
        As[0][la_ks + 6][la_row] = va1.z; As[0][la_ks + 7][la_row] = va1.w;
        float4 vb0 = *(const float4*)Bbase;
        float4 vb1 = *(const float4*)(Bbase + 4);
        *(float4*)&Bs[0][lb_k][lb_n0] = vb0;
        *(float4*)&Bs[0][lb_k][lb_n0 + 4] = vb1;
    }
    __syncthreads();

    int buf = 0;
    for (int k0 = 0; k0 < 256; k0 += BK) {
        float4 va0 = make_float4(0.f, 0.f, 0.f, 0.f), va1 = va0, vb0 = va0, vb1 = va0;
        bool more = (k0 + BK) < 256;
        if (more) {
            if (arow_ok) {
                const float* Ap = Abase + k0 + BK;
                va0 = *(const float4*)Ap;
                va1 = *(const float4*)(Ap + 4);
            }
            const float* Bp = Bbase + (size_t)(k0 + BK) * HC;
            vb0 = *(const float4*)Bp;
            vb1 = *(const float4*)(Bp + 4);
        }

#pragma unroll
        for (int kk = 0; kk < BK; kk++) {
            float4 a0 = *(const float4*)&As[buf][kk][ty * 8];
            float4 a1 = *(const float4*)&As[buf][kk][ty * 8 + 4];
            unsigned long long ad[8];
            ad[0] = dupr(a0.x); ad[1] = dupr(a0.y); ad[2] = dupr(a0.z); ad[3] = dupr(a0.w);
            ad[4] = dupr(a1.x); ad[5] = dupr(a1.y); ad[6] = dupr(a1.z); ad[7] = dupr(a1.w);
            ulonglong2 b01 = *(const ulonglong2*)&Bs[buf][kk][tx * 8];
            ulonglong2 b23 = *(const ulonglong2*)&Bs[buf][kk][tx * 8 + 4];
            unsigned long long bp[4] = {b01.x, b01.y, b23.x, b23.y};
#pragma unroll
            for (int m = 0; m < 8; m++) {
                FMA2(acc[m][0], ad[m], bp[0]);
                FMA2(acc[m][1], ad[m], bp[1]);
                FMA2(acc[m][2], ad[m], bp[2]);
                FMA2(acc[m][3], ad[m], bp[3]);
            }
        }

        if (more) {
            int nb = buf ^ 1;
            __syncthreads();
            As[nb][la_ks + 0][la_row] = va0.x; As[nb][la_ks + 1][la_row] = va0.y;
            As[nb][la_ks + 2][la_row] = va0.z; As[nb][la_ks + 3][la_row] = va0.w;
            As[nb][la_ks + 4][la_row] = va1.x; As[nb][la_ks + 5][la_row] = va1.y;
            As[nb][la_ks + 6][la_row] = va1.z; As[nb][la_ks + 7][la_row] = va1.w;
            *(float4*)&Bs[nb][lb_k][lb_n0] = vb0;
            *(float4*)&Bs[nb][lb_k][lb_n0 + 4] = vb1;
            __syncthreads();
            buf = nb;
        }
    }

    float asr[8], adr[8];
#pragma unroll
    for (int j = 0; j < 8; j++) {
        asr[j] = __ldg(&asrc[bn + tx * 8 + j]);
        adr[j] = __ldg(&adst[bn + tx * 8 + j]);
    }
    int head = (bn >> 6) + (tx >> 3);   // 2 heads per BN=128

#pragma unroll
    for (int m = 0; m < 8; m++) {
        int row = bm + ty * 8 + m;
        float f[8];
        f[0] = __uint_as_float((unsigned)acc[m][0]);
        f[1] = __uint_as_float((unsigned)(acc[m][0] >> 32));
        f[2] = __uint_as_float((unsigned)acc[m][1]);
        f[3] = __uint_as_float((unsigned)(acc[m][1] >> 32));
        f[4] = __uint_as_float((unsigned)acc[m][2]);
        f[5] = __uint_as_float((unsigned)(acc[m][2] >> 32));
        f[6] = __uint_as_float((unsigned)acc[m][3]);
        f[7] = __uint_as_float((unsigned)(acc[m][3] >> 32));

        float ps = 0.f, pd = 0.f;
#pragma unroll
        for (int j = 0; j < 8; j++) {
            ps = fmaf(f[j], asr[j], ps);
            pd = fmaf(f[j], adr[j], pd);
        }
#pragma unroll
        for (int o = 1; o < 8; o <<= 1) {
            ps += __shfl_xor_sync(0xFFFFFFFFu, ps, o);
            pd += __shfl_xor_sync(0xFFFFFFFFu, pd, o);
        }

        if (row < Nn) {
            __half2 ph[4];
            ph[0] = __floats2half2_rn(f[0], f[1]);
            ph[1] = __floats2half2_rn(f[2], f[3]);
            ph[2] = __floats2half2_rn(f[4], f[5]);
            ph[3] = __floats2half2_rn(f[6], f[7]);
            *(uint4*)&g_hh[(size_t)row * HC + bn + tx * 8] = *(uint4*)ph;
            if ((tx & 7) == 0) {
                g_es[row * Hh + head] = ps;
                g_ed[row * Hh + head] = pd;
            }
        }
    }
}

// ---------------- GAT aggregation: warp per dst node, SINGLE PASS ----------
// mode 0: write fp32 g_x; mode 1: fused projection + per-graph pooling.
__global__ void __launch_bounds__(256) k_agg(const float* __restrict__ bias,
                                             const float* __restrict__ Wp,
                                             const int* __restrict__ batch,
                                             int mode) {
    int w = (blockIdx.x * blockDim.x + threadIdx.x) >> 5;
    if (w >= Nn) return;
    int lane = threadIdx.x & 31;

    int r0 = g_off[w];
    int r1 = g_off[w + 1];
    float4 ed4 = *(const float4*)(g_ed + w * Hh);

    int hsel = lane >> 3;
    float edh = (hsel == 0) ? ed4.x : (hsel == 1) ? ed4.y : (hsel == 2) ? ed4.z : ed4.w;

    const float* es = (const float*)g_es;

    float a0 = 0.f, a1 = 0.f, a2 = 0.f, a3 = 0.f, a4 = 0.f, a5 = 0.f, a6 = 0.f, a7 = 0.f;
    float den = 0.f;
    int i = r0;
#define ACC_EDGE(qq, ww)                                            \
    {                                                               \
        float2 f0 = __half22float2(*(__half2*)&qq.x);               \
        float2 f1 = __half22float2(*(__half2*)&qq.y);               \
        float2 f2 = __half22float2(*(__half2*)&qq.z);               \
        float2 f3 = __half22float2(*(__half2*)&qq.w);               \
        a0 = fmaf(ww, f0.x, a0); a1 = fmaf(ww, f0.y, a1);           \
        a2 = fmaf(ww, f1.x, a2); a3 = fmaf(ww, f1.y, a3);           \
        a4 = fmaf(ww, f2.x, a4); a5 = fmaf(ww, f2.y, a5);           \
        a6 = fmaf(ww, f3.x, a6); a7 = fmaf(ww, f3.y, a7);           \
    }
    for (; i + 4 <= r1; i += 4) {
        int s0 = __ldg(&g_csr[i]);
        int s1 = __ldg(&g_csr[i + 1]);
        int s2 = __ldg(&g_csr[i + 2]);
        int s3 = __ldg(&g_csr[i + 3]);
        float e0 = __ldg(&es[s0 * 4 + hsel]);
        float e1 = __ldg(&es[s1 * 4 + hsel]);
        float e2 = __ldg(&es[s2 * 4 + hsel]);
        float e3 = __ldg(&es[s3 * 4 + hsel]);
        uint4 q0 = *(const uint4*)(g_hh + (size_t)s0 * HC + lane * 8);
        uint4 q1 = *(const uint4*)(g_hh + (size_t)s1 * HC + lane * 8);
        uint4 q2 = *(const uint4*)(g_hh + (size_t)s2 * HC + lane * 8);
        uint4 q3 = *(const uint4*)(g_hh + (size_t)s3 * HC + lane * 8);
        float w0 = __expf(lrelu(e0 + edh));
        float w1 = __expf(lrelu(e1 + edh));
        float w2 = __expf(lrelu(e2 + edh));
        float w3 = __expf(lrelu(e3 + edh));
        den += w0 + w1 + w2 + w3;
        ACC_EDGE(q0, w0);
        ACC_EDGE(q1, w1);
        ACC_EDGE(q2, w2);
        ACC_EDGE(q3, w3);
    }
    for (; i < r1; i++) {
        int s0 = __ldg(&g_csr[i]);
        float e0 = __ldg(&es[s0 * 4 + hsel]);
        uint4 q0 = *(const uint4*)(g_hh + (size_t)s0 * HC + lane * 8);
        float w0 = __expf(lrelu(e0 + edh));
        den += w0;
        ACC_EDGE(q0, w0);
    }
#undef ACC_EDGE

    float inv = 1.0f / fmaxf(den, 1e-16f);

    int b0 = lane * 8;
    const float4* bp4 = (const float4*)(bias + b0);
    float4 bb0 = bp4[0], bb1 = bp4[1];
    float v[8];
    v[0] = fmaxf(a0 * inv + bb0.x, 0.0f);
    v[1] = fmaxf(a1 * inv + bb0.y, 0.0f);
    v[2] = fmaxf(a2 * inv + bb0.z, 0.0f);
    v[3] = fmaxf(a3 * inv + bb0.w, 0.0f);
    v[4] = fmaxf(a4 * inv + bb1.x, 0.0f);
    v[5] = fmaxf(a5 * inv + bb1.y, 0.0f);
    v[6] = fmaxf(a6 * inv + bb1.z, 0.0f);
    v[7] = fmaxf(a7 * inv + bb1.w, 0.0f);

    if (mode == 0) {
        float* op = g_x + (size_t)w * HC + b0;
        *(float4*)op = make_float4(v[0], v[1], v[2], v[3]);
        *(float4*)(op + 4) = make_float4(v[4], v[5], v[6], v[7]);
    } else {
        float acc = 0.0f;
#pragma unroll 4
        for (int sl = 0; sl < 32; sl++) {
#pragma unroll
            for (int j = 0; j < 8; j++) {
                float xb = __shfl_sync(0xFFFFFFFFu, v[j], sl);
                acc = fmaf(xb, __ldg(&Wp[(size_t)(sl * 8 + j) * DOUT + lane]), acc);
            }
        }
        int g = __ldg(&batch[w]);
        atomicAdd(&g_sums[g * DOUT + lane], acc);
        if (lane == 0) atomicAdd(&g_cnt[g], 1);
    }
}

// ---------------- final mean + bias ----------------
__global__ void k_fin(float* __restrict__ out, const float* __restrict__ bp) {
    int i = blockIdx.x * blockDim.x + threadIdx.x;
    if (i >= Gg * DOUT) return;
    int g = i / DOUT, j = i % DOUT;
    out[i] = g_sums[i] / fmaxf((float)g_cnt[g], 1.0f) + bp[j];
}

// ---------------- launch ----------------
extern "C" void kernel_launch(void* const* d_in, const int* in_sizes, int n_in,
                              void* d_out, int out_size) {
    const float* x     = (const float*)d_in[0];
    const int*   ei    = (const int*)d_in[1];
    const int*   batch = (const int*)d_in[2];
    const float* W1    = (const float*)d_in[3];
    const float* as1   = (const float*)d_in[4];
    const float* ad1   = (const float*)d_in[5];
    const float* b1    = (const float*)d_in[6];
    const float* W2    = (const float*)d_in[7];
    const float* as2   = (const float*)d_in[8];
    const float* ad2   = (const float*)d_in[9];
    const float* b2    = (const float*)d_in[10];
    const float* Wp    = (const float*)d_in[11];
    const float* bp    = (const float*)d_in[12];
    float* out = (float*)d_out;

    (void)in_sizes; (void)n_in; (void)out_size;

    // Second stream + events for CSR||GEMM overlap (host objects, created once).
    static cudaStream_t s2 = nullptr;
    static cudaEvent_t ev_fork = nullptr, ev_join = nullptr;
    if (s2 == nullptr) {
        cudaStreamCreateWithFlags(&s2, cudaStreamNonBlocking);
        cudaEventCreateWithFlags(&ev_fork, cudaEventDisableTiming);
        cudaEventCreateWithFlags(&ev_join, cudaEventDisableTiming);
    }

    dim3 ggrid((Nn + BM - 1) / BM, HC / BN);  // (157, 2)
    int warp_blocks = (Nn * 32 + 255) / 256;  // 2500

    // Fork: CSR build on s2, layer-1 GEMM on the main stream, in parallel.
    cudaEventRecord(ev_fork, 0);
    cudaStreamWaitEvent(s2, ev_fork, 0);
    k_zero<<<(Nn + 255) / 256, 256, 0, s2>>>();
    k_count<<<(Ee / 8 + 255) / 256, 256, 0, s2>>>(ei);
    k_scan<<<1, 1024, 0, s2>>>();
    k_scatter<<<(Ee / 8 + Nn + 255) / 256, 256, 0, s2>>>(ei);
    cudaEventRecord(ev_join, s2);

    k_gemm<<<ggrid, 256>>>(x, W1, as1, ad1, 1);          // layer-1 GEMM (main)

    // Join: agg1 needs both CSR and GEMM-1 results.
    cudaStreamWaitEvent(0, ev_join, 0);
    k_agg<<<warp_blocks, 256>>>(b1, Wp, batch, 0);       // layer-1 agg -> g_x

    k_gemm<<<ggrid, 256>>>(nullptr, W2, as2, ad2, 0);    // layer-2 GEMM
    k_agg<<<warp_blocks, 256>>>(b2, Wp, batch, 1);       // layer-2 agg + proj + pool

    k_fin<<<(Gg * DOUT + 255) / 256, 256>>>(out, bp);
}